// round 4
// baseline (speedup 1.0000x reference)
#include <cuda_runtime.h>
#include <cstdint>
#include <cstddef>

// ---------------------------------------------------------------------------
// Scratch (static __device__ arrays; no allocation anywhere)
// ---------------------------------------------------------------------------
__device__ float g_xn[4096 * 1024];   // xn (pass 1) then xn2 (pass 2)
__device__ float g_q [4096 * 1024];
__device__ float g_k [2048 * 1024];
__device__ float g_v [4096 * 1024];
__device__ float g_at[4096 * 1024];
__device__ float g_xm[4096 * 1024];   // x + attn proj (residual mid)
__device__ float g_h [4096 * 4096];   // FFN hidden

// ---------------------------------------------------------------------------
// f32x2 packed helpers (sm_103a FFMA2 path — PTX only)
// ---------------------------------------------------------------------------
__device__ __forceinline__ unsigned long long pk2(float lo, float hi) {
    unsigned long long r;
    asm("mov.b64 %0, {%1, %2};" : "=l"(r) : "f"(lo), "f"(hi));
    return r;
}
__device__ __forceinline__ float2 upk2(unsigned long long v) {
    float2 r;
    asm("mov.b64 {%0, %1}, %2;" : "=f"(r.x), "=f"(r.y) : "l"(v));
    return r;
}
__device__ __forceinline__ void ffma2(unsigned long long& c, unsigned long long a,
                                      unsigned long long b) {
    asm("fma.rn.f32x2 %0, %1, %2, %0;" : "+l"(c) : "l"(a), "l"(b));
}
__device__ __forceinline__ unsigned long long mul2(unsigned long long a,
                                                   unsigned long long b) {
    unsigned long long r;
    asm("mul.rn.f32x2 %0, %1, %2;" : "=l"(r) : "l"(a), "l"(b));
    return r;
}

__device__ __forceinline__ float siluf(float z) { return z / (1.0f + expf(-z)); }

// ---------------------------------------------------------------------------
// SGEMM: C[M,N] = A[M,K] * B[N,K]^T   (both operands K-contiguous)
// 128x128x8 block tile, 256 threads, 8x8 per-thread microtile, f32x2 FMA.
// EPI: 0 = store   1 = res + acc + bias   2 = acc + bias
//      3 = silu(res) * (acc + bias)   (res = h1, in-place gate)
// All shapes are multiples of the tile — no bounds checks.
// ---------------------------------------------------------------------------
#define BM 128
#define BN 128
#define BKK 8

template <int EPI>
__global__ __launch_bounds__(256)
void sgemm_kernel(const float* __restrict__ A, const float* __restrict__ B,
                  const float* __restrict__ bias, const float* __restrict__ res,
                  float* __restrict__ C, int M, int N, int K)
{
    __shared__ float As[2][BKK][BM + 4];
    __shared__ float Bs[2][BKK][BN + 4];

    const int tid = threadIdx.x;
    const int bm = blockIdx.y * BM;
    const int bn = blockIdx.x * BN;

    // global->smem loader mapping: one float4 per thread per operand per tile
    const int lrow = tid >> 1;          // 0..127
    const int lcol = (tid & 1) * 4;     // 0 or 4
    const float* Aptr = A + (size_t)(bm + lrow) * K + lcol;
    const float* Bptr = B + (size_t)(bn + lrow) * K + lcol;

    const int tx = tid & 15;            // 0..15 -> cols
    const int ty = tid >> 4;            // 0..15 -> rows

    unsigned long long acc[4][8];       // row-pairs x 8 cols
#pragma unroll
    for (int i = 0; i < 4; ++i)
#pragma unroll
        for (int j = 0; j < 8; ++j) acc[i][j] = 0ULL;

    const int ktiles = K / BKK;

    // prologue: tile 0
    {
        float4 a4 = *(const float4*)Aptr;
        float4 b4 = *(const float4*)Bptr;
        As[0][lcol + 0][lrow] = a4.x; As[0][lcol + 1][lrow] = a4.y;
        As[0][lcol + 2][lrow] = a4.z; As[0][lcol + 3][lrow] = a4.w;
        Bs[0][lcol + 0][lrow] = b4.x; Bs[0][lcol + 1][lrow] = b4.y;
        Bs[0][lcol + 2][lrow] = b4.z; Bs[0][lcol + 3][lrow] = b4.w;
    }
    __syncthreads();

    int buf = 0;
    for (int kt = 0; kt < ktiles; ++kt) {
        float4 na, nb;
        const bool has = (kt + 1 < ktiles);
        if (has) {
            na = *(const float4*)(Aptr + (kt + 1) * BKK);
            nb = *(const float4*)(Bptr + (kt + 1) * BKK);
        }

#pragma unroll
        for (int k = 0; k < BKK; ++k) {
            float4 a0 = *(const float4*)&As[buf][k][ty * 4];
            float4 a1 = *(const float4*)&As[buf][k][64 + ty * 4];
            float4 b0 = *(const float4*)&Bs[buf][k][tx * 4];
            float4 b1 = *(const float4*)&Bs[buf][k][64 + tx * 4];
            unsigned long long ap[4];
            ap[0] = pk2(a0.x, a0.y); ap[1] = pk2(a0.z, a0.w);
            ap[2] = pk2(a1.x, a1.y); ap[3] = pk2(a1.z, a1.w);
            float bv[8] = {b0.x, b0.y, b0.z, b0.w, b1.x, b1.y, b1.z, b1.w};
#pragma unroll
            for (int c = 0; c < 8; ++c) {
                unsigned long long bd = pk2(bv[c], bv[c]);
#pragma unroll
                for (int rp = 0; rp < 4; ++rp) ffma2(acc[rp][c], ap[rp], bd);
            }
        }

        if (has) {
            int nb2 = buf ^ 1;
            As[nb2][lcol + 0][lrow] = na.x; As[nb2][lcol + 1][lrow] = na.y;
            As[nb2][lcol + 2][lrow] = na.z; As[nb2][lcol + 3][lrow] = na.w;
            Bs[nb2][lcol + 0][lrow] = nb.x; Bs[nb2][lcol + 1][lrow] = nb.y;
            Bs[nb2][lcol + 2][lrow] = nb.z; Bs[nb2][lcol + 3][lrow] = nb.w;
        }
        __syncthreads();
        buf ^= 1;
    }

    // unpack accumulators: rows r=0..3 -> ty*4+r, r=4..7 -> 64+ty*4+(r-4)
    float Cr[8][8];
#pragma unroll
    for (int rp = 0; rp < 4; ++rp)
#pragma unroll
        for (int c = 0; c < 8; ++c) {
            float2 p = upk2(acc[rp][c]);
            Cr[rp * 2 + 0][c] = p.x;
            Cr[rp * 2 + 1][c] = p.y;
        }

#pragma unroll
    for (int r = 0; r < 8; ++r) {
        const int gr = bm + ((r < 4) ? (ty * 4 + r) : (64 + ty * 4 + (r - 4)));
        const size_t rowoff = (size_t)gr * N;
        const int n0 = bn + tx * 4;
        const int n1 = bn + 64 + tx * 4;
        float4 o0 = make_float4(Cr[r][0], Cr[r][1], Cr[r][2], Cr[r][3]);
        float4 o1 = make_float4(Cr[r][4], Cr[r][5], Cr[r][6], Cr[r][7]);

        if (EPI == 1) {
            float4 b0 = *(const float4*)(bias + n0);
            float4 b1 = *(const float4*)(bias + n1);
            float4 r0 = *(const float4*)(res + rowoff + n0);
            float4 r1 = *(const float4*)(res + rowoff + n1);
            o0.x += b0.x + r0.x; o0.y += b0.y + r0.y; o0.z += b0.z + r0.z; o0.w += b0.w + r0.w;
            o1.x += b1.x + r1.x; o1.y += b1.y + r1.y; o1.z += b1.z + r1.z; o1.w += b1.w + r1.w;
        } else if (EPI == 2) {
            float4 b0 = *(const float4*)(bias + n0);
            float4 b1 = *(const float4*)(bias + n1);
            o0.x += b0.x; o0.y += b0.y; o0.z += b0.z; o0.w += b0.w;
            o1.x += b1.x; o1.y += b1.y; o1.z += b1.z; o1.w += b1.w;
        } else if (EPI == 3) {
            float4 b0 = *(const float4*)(bias + n0);
            float4 b1 = *(const float4*)(bias + n1);
            float4 h0 = *(const float4*)(res + rowoff + n0);
            float4 h1v = *(const float4*)(res + rowoff + n1);
            o0.x = siluf(h0.x)  * (o0.x + b0.x);
            o0.y = siluf(h0.y)  * (o0.y + b0.y);
            o0.z = siluf(h0.z)  * (o0.z + b0.z);
            o0.w = siluf(h0.w)  * (o0.w + b0.w);
            o1.x = siluf(h1v.x) * (o1.x + b1.x);
            o1.y = siluf(h1v.y) * (o1.y + b1.y);
            o1.z = siluf(h1v.z) * (o1.z + b1.z);
            o1.w = siluf(h1v.w) * (o1.w + b1.w);
        }
        *(float4*)(C + rowoff + n0) = o0;
        *(float4*)(C + rowoff + n1) = o1;
    }
}

// ---------------------------------------------------------------------------
// RMSNorm (optionally with sigmoid-gated blend of x and x_token)
// one block per row, 256 threads, D=1024
// ---------------------------------------------------------------------------
__global__ __launch_bounds__(256)
void rms_kernel(const float* __restrict__ X, const float* __restrict__ XT,
                const float* __restrict__ lcw, const float* __restrict__ W,
                float* __restrict__ out, int gated)
{
    const int row = blockIdx.x;
    const int tid = threadIdx.x;
    float4 xv = ((const float4*)(X + (size_t)row * 1024))[tid];
    if (gated) {
        float lc = 1.0f / (1.0f + expf(-lcw[0]));
        float om = 1.0f - lc;
        float4 tv = ((const float4*)(XT + (size_t)row * 1024))[tid];
        xv.x = lc * xv.x + om * tv.x;
        xv.y = lc * xv.y + om * tv.y;
        xv.z = lc * xv.z + om * tv.z;
        xv.w = lc * xv.w + om * tv.w;
    }
    float ss = xv.x * xv.x + xv.y * xv.y + xv.z * xv.z + xv.w * xv.w;
#pragma unroll
    for (int o = 16; o > 0; o >>= 1) ss += __shfl_xor_sync(0xffffffffu, ss, o);
    __shared__ float red[8];
    if ((tid & 31) == 0) red[tid >> 5] = ss;
    __syncthreads();
    float tot = red[0] + red[1] + red[2] + red[3] + red[4] + red[5] + red[6] + red[7];
    float rinv = rsqrtf(tot * (1.0f / 1024.0f) + 1e-5f);
    float4 wv = ((const float4*)W)[tid];
    float4 ov;
    ov.x = xv.x * rinv * wv.x;
    ov.y = xv.y * rinv * wv.y;
    ov.z = xv.z * rinv * wv.z;
    ov.w = xv.w * rinv * wv.w;
    ((float4*)(out + (size_t)row * 1024))[tid] = ov;
}

// ---------------------------------------------------------------------------
// Causal attention, flash-style online softmax.
// Q [B,T,H,HD], K [T,H,HD] (no batch dim), V [B,T,H,HD], out [B,T,H,HD]
// One block = (b, h, 128 query rows). One thread = one query row.
// q and o live in registers (64 each); K/V streamed through smem in 64-key
// tiles, read as broadcast LDS.64 f32x2 operands.
// scale = D^-0.5 = 1/32 (full model dim, per reference).
// ---------------------------------------------------------------------------
__global__ __launch_bounds__(128)
void attn_kernel(const float* __restrict__ Q, const float* __restrict__ Kg,
                 const float* __restrict__ V, float* __restrict__ O)
{
    __shared__ float Ks[64][64];
    __shared__ float Vs[64][64];

    const int qt = blockIdx.x, h = blockIdx.y, b = blockIdx.z;
    const int q0 = qt * 128;
    const int tid = threadIdx.x;
    const int qidx = q0 + tid;

    unsigned long long q2[32], o2[32];
    {
        const float4* qp = (const float4*)(Q + (((size_t)(b * 2048 + qidx)) * 16 + h) * 64);
#pragma unroll
        for (int i = 0; i < 16; ++i) {
            float4 v = qp[i];
            q2[2 * i]     = pk2(v.x, v.y);
            q2[2 * i + 1] = pk2(v.z, v.w);
        }
    }
#pragma unroll
    for (int i = 0; i < 32; ++i) o2[i] = 0ULL;

    float mval = __int_as_float(0xff800000);  // -inf
    float l = 0.0f;
    const float scale = 0.03125f;

    for (int kt = 0; kt < q0 + 128; kt += 64) {
        __syncthreads();
#pragma unroll
        for (int i = 0; i < 8; ++i) {
            int u = tid + i * 128;            // over [64 rows][16 float4]
            int row = u >> 4, c4 = u & 15;
            ((float4*)&Ks[row][0])[c4] =
                *(const float4*)(Kg + (size_t)(kt + row) * 1024 + h * 64 + c4 * 4);
            ((float4*)&Vs[row][0])[c4] =
                *(const float4*)(V + (((size_t)(b * 2048 + kt + row)) * 16 + h) * 64 + c4 * 4);
        }
        __syncthreads();

        int jmax = qidx - kt + 1;
        if (jmax > 64) jmax = 64;
        for (int j = 0; j < jmax; ++j) {
            const unsigned long long* kp = (const unsigned long long*)&Ks[j][0];
            unsigned long long s2 = 0ULL;
#pragma unroll
            for (int d = 0; d < 32; ++d) ffma2(s2, q2[d], kp[d]);
            float2 sp = upk2(s2);
            float s = (sp.x + sp.y) * scale;

            const unsigned long long* vp = (const unsigned long long*)&Vs[j][0];
            if (s <= mval) {
                float p = __expf(s - mval);
                l += p;
                unsigned long long pd = pk2(p, p);
#pragma unroll
                for (int d = 0; d < 32; ++d) ffma2(o2[d], pd, vp[d]);
            } else {
                float f = __expf(mval - s);   // exp(-inf)=0 on first key
                mval = s;
                l = l * f + 1.0f;
                unsigned long long fd = pk2(f, f);
#pragma unroll
                for (int d = 0; d < 32; ++d) {
                    unsigned long long t = vp[d];    // t = o*f + v
                    ffma2(t, o2[d], fd);
                    o2[d] = t;
                }
            }
        }
    }

    float inv = 1.0f / l;
    unsigned long long iv = pk2(inv, inv);
    float* op = O + (((size_t)(b * 2048 + qidx)) * 16 + h) * 64;
#pragma unroll
    for (int i = 0; i < 16; ++i) {
        float2 p0 = upk2(mul2(o2[2 * i], iv));
        float2 p1 = upk2(mul2(o2[2 * i + 1], iv));
        *(float4*)(op + i * 4) = make_float4(p0.x, p0.y, p1.x, p1.y);
    }
}

// ---------------------------------------------------------------------------
// Launch: 10 kernels, single stream, graph-capturable.
// ---------------------------------------------------------------------------
extern "C" void kernel_launch(void* const* d_in, const int* in_sizes, int n_in,
                              void* d_out, int out_size)
{
    const float* x       = (const float*)d_in[0];
    const float* x_token = (const float*)d_in[1];
    const float* pos_emb = (const float*)d_in[2];
    const float* lcw     = (const float*)d_in[3];
    const float* Wq      = (const float*)d_in[4];
    const float* Wk      = (const float*)d_in[5];
    const float* Wv      = (const float*)d_in[6];
    const float* proj_w  = (const float*)d_in[7];
    const float* proj_b  = (const float*)d_in[8];
    const float* w1_w    = (const float*)d_in[9];
    const float* w1_b    = (const float*)d_in[10];
    const float* w2_w    = (const float*)d_in[11];
    const float* w2_b    = (const float*)d_in[12];
    const float* w3_w    = (const float*)d_in[13];
    const float* w3_b    = (const float*)d_in[14];
    const float* n1w     = (const float*)d_in[15];
    const float* n2w     = (const float*)d_in[16];
    float* out = (float*)d_out;

    float *xn, *q, *k, *v, *at, *xm, *hbuf;
    cudaGetSymbolAddress((void**)&xn,   g_xn);
    cudaGetSymbolAddress((void**)&q,    g_q);
    cudaGetSymbolAddress((void**)&k,    g_k);
    cudaGetSymbolAddress((void**)&v,    g_v);
    cudaGetSymbolAddress((void**)&at,   g_at);
    cudaGetSymbolAddress((void**)&xm,   g_xm);
    cudaGetSymbolAddress((void**)&hbuf, g_h);

    // 1) gated rmsnorm -> xn
    rms_kernel<<<4096, 256>>>(x, x_token, lcw, n1w, xn, 1);
    // 2) q = xn @ Wq^T ; k = pos_emb @ Wk^T ; v = xn @ Wv^T
    sgemm_kernel<0><<<dim3(8, 32), 256>>>(xn,      Wq, nullptr, nullptr, q, 4096, 1024, 1024);
    sgemm_kernel<0><<<dim3(8, 16), 256>>>(pos_emb, Wk, nullptr, nullptr, k, 2048, 1024, 1024);
    sgemm_kernel<0><<<dim3(8, 32), 256>>>(xn,      Wv, nullptr, nullptr, v, 4096, 1024, 1024);
    // 3) causal attention
    attn_kernel<<<dim3(16, 16, 2), 128>>>(q, k, v, at);
    // 4) x_mid = x + attn @ proj_w^T + proj_b
    sgemm_kernel<1><<<dim3(8, 32), 256>>>(at, proj_w, proj_b, x, xm, 4096, 1024, 1024);
    // 5) xn2 = rmsnorm(x_mid)
    rms_kernel<<<4096, 256>>>(xm, nullptr, nullptr, n2w, xn, 0);
    // 6) h1 = xn2 @ w1^T + b1 ; h = silu(h1) * (xn2 @ w3^T + b3)  (in place)
    sgemm_kernel<2><<<dim3(32, 32), 256>>>(xn, w1_w, w1_b, nullptr, hbuf, 4096, 4096, 1024);
    sgemm_kernel<3><<<dim3(32, 32), 256>>>(xn, w3_w, w3_b, hbuf,    hbuf, 4096, 4096, 1024);
    // 7) out = x_mid + h @ w2^T + b2
    sgemm_kernel<1><<<dim3(8, 32), 256>>>(hbuf, w2_w, w2_b, xm, out, 4096, 1024, 4096);
}

// round 7
// speedup vs baseline: 1.3832x; 1.3832x over previous
#include <cuda_runtime.h>
#include <cuda_bf16.h>
#include <cstdint>
#include <cstddef>

// ---------------------------------------------------------------------------
// Scratch (static __device__ arrays; no allocation anywhere)
// ---------------------------------------------------------------------------
__device__ float g_xn[4096 * 1024];   // xn (pass 1) then xn2 (pass 2)
__device__ float g_q [4096 * 1024];
__device__ float g_k [2048 * 1024];
__device__ float g_v [4096 * 1024];
__device__ float g_at[4096 * 1024];
__device__ float g_xm[4096 * 1024];   // x + attn proj (residual mid)
__device__ float g_h [4096 * 4096];   // FFN hidden

// ---------------------------------------------------------------------------
// f32x2 packed helpers (attention path)
// ---------------------------------------------------------------------------
__device__ __forceinline__ unsigned long long pk2(float lo, float hi) {
    unsigned long long r;
    asm("mov.b64 %0, {%1, %2};" : "=l"(r) : "f"(lo), "f"(hi));
    return r;
}
__device__ __forceinline__ float2 upk2(unsigned long long v) {
    float2 r;
    asm("mov.b64 {%0, %1}, %2;" : "=f"(r.x), "=f"(r.y) : "l"(v));
    return r;
}
__device__ __forceinline__ void ffma2(unsigned long long& c, unsigned long long a,
                                      unsigned long long b) {
    asm("fma.rn.f32x2 %0, %1, %2, %0;" : "+l"(c) : "l"(a), "l"(b));
}
__device__ __forceinline__ unsigned long long mul2(unsigned long long a,
                                                   unsigned long long b) {
    unsigned long long r;
    asm("mul.rn.f32x2 %0, %1, %2;" : "=l"(r) : "l"(a), "l"(b));
    return r;
}

__device__ __forceinline__ float siluf(float z) { return z / (1.0f + expf(-z)); }

// ---------------------------------------------------------------------------
// mma.sync / ldmatrix helpers (plain sm_103-legal PTX; executes as HMMA)
// ---------------------------------------------------------------------------
__device__ __forceinline__ uint32_t smem_u32(const void* p) {
    uint32_t a;
    asm("{ .reg .u64 t; cvta.to.shared.u64 t, %1; cvt.u32.u64 %0, t; }"
        : "=r"(a) : "l"(p));
    return a;
}
__device__ __forceinline__ void ldmx4(uint32_t* r, uint32_t addr) {
    asm volatile("ldmatrix.sync.aligned.m8n8.x4.shared.b16 {%0,%1,%2,%3}, [%4];"
                 : "=r"(r[0]), "=r"(r[1]), "=r"(r[2]), "=r"(r[3]) : "r"(addr));
}
__device__ __forceinline__ void mma16816(float* d, const uint32_t* a,
                                         const uint32_t* b) {
    asm volatile(
        "mma.sync.aligned.m16n8k16.row.col.f32.bf16.bf16.f32 "
        "{%0,%1,%2,%3}, {%4,%5,%6,%7}, {%8,%9}, {%0,%1,%2,%3};"
        : "+f"(d[0]), "+f"(d[1]), "+f"(d[2]), "+f"(d[3])
        : "r"(a[0]), "r"(a[1]), "r"(a[2]), "r"(a[3]), "r"(b[0]), "r"(b[1]));
}

// ---------------------------------------------------------------------------
// Tensor-core GEMM: C[M,N] = A[M,K] * B[N,K]^T, fp32 in/out.
// bf16 hi/lo 3-term: A*B ~= Ah*Bh + Ah*Bl + Al*Bh  (rel err ~2^-17)
// 128x128x32 tile, 256 threads = 8 warps (2 M x 4 N), warp tile 64x32.
// smem row layout: 128 bytes = [hi: 64B (32 bf16)] [lo: 64B], 16B chunks
// xor-swizzled by (row & 7).  Double buffered: 2 x 32KB = 64KB dynamic smem.
// EPI: 0 store | 1 res+acc+bias | 2 acc+bias | 3 silu(res)*(acc+bias)
// ---------------------------------------------------------------------------
#define MBM 128
#define MBN 128
#define MBK 32
#define STAGE 32768               // A 16KB + B 16KB
#define MM_SMEM (2 * STAGE)

// fp32 float4 -> bf16 hi/lo, into swizzled row
__device__ __forceinline__ void stash(char* base, int row, int k4, float4 v) {
    __nv_bfloat16 h0 = __float2bfloat16(v.x), h1 = __float2bfloat16(v.y),
                  h2 = __float2bfloat16(v.z), h3 = __float2bfloat16(v.w);
    __nv_bfloat16 l0 = __float2bfloat16(v.x - __bfloat162float(h0));
    __nv_bfloat16 l1 = __float2bfloat16(v.y - __bfloat162float(h1));
    __nv_bfloat16 l2 = __float2bfloat16(v.z - __bfloat162float(h2));
    __nv_bfloat16 l3 = __float2bfloat16(v.w - __bfloat162float(h3));
    uint2 hp, lp;
    hp.x = (uint32_t)__bfloat16_as_ushort(h0) | ((uint32_t)__bfloat16_as_ushort(h1) << 16);
    hp.y = (uint32_t)__bfloat16_as_ushort(h2) | ((uint32_t)__bfloat16_as_ushort(h3) << 16);
    lp.x = (uint32_t)__bfloat16_as_ushort(l0) | ((uint32_t)__bfloat16_as_ushort(l1) << 16);
    lp.y = (uint32_t)__bfloat16_as_ushort(l2) | ((uint32_t)__bfloat16_as_ushort(l3) << 16);
    const int sub = (k4 & 1) * 8;
    const int ch  = k4 >> 1;                       // hi chunks 0..3
    const int sw  = row & 7;
    *(uint2*)(base + row * 128 + ((ch       ^ sw) << 4) + sub) = hp;
    *(uint2*)(base + row * 128 + (((ch + 4) ^ sw) << 4) + sub) = lp;
}

template <int EPI>
__global__ __launch_bounds__(256)
void mma_gemm(const float* __restrict__ A, const float* __restrict__ B,
              const float* __restrict__ bias, const float* __restrict__ res,
              float* __restrict__ C, int M, int N, int K)
{
    extern __shared__ char smem[];
    const int tid = threadIdx.x;
    const int wid = tid >> 5;
    const int lid = tid & 31;
    const int warp_m = wid >> 2;          // 0..1
    const int warp_n = wid & 3;           // 0..3
    const int bm = blockIdx.y * MBM;
    const int bn = blockIdx.x * MBN;

    const int g   = lid >> 2;             // groupID 0..7
    const int tig = lid & 3;
    const int mat = lid >> 3;             // ldmatrix matrix id 0..3
    const int rwi = lid & 7;

    // per-lane invariant parts of ldmatrix addressing
    const int rowA_base = warp_m * 64 + rwi + (mat & 1) * 8;   // + am*16
    const int khA_sel   = mat >> 1;                            // k-half select
    const int rowB_base = warp_n * 32 + (mat >> 1) * 8 + rwi;  // + pair*16
    const int khB_sel   = mat & 1;

    float acc[4][4][4];
#pragma unroll
    for (int i = 0; i < 4; ++i)
#pragma unroll
        for (int j = 0; j < 4; ++j)
#pragma unroll
            for (int q = 0; q < 4; ++q) acc[i][j][q] = 0.0f;

    const float* Abase = A + (size_t)bm * K;
    const float* Bbase = B + (size_t)bn * K;
    const int nchunks = K / MBK;

    // loader lane mapping: u = tid + i*256 ; row = u>>3, k4 = u&7 (8 float4/row)
    const int lrow = tid >> 3;
    const int lk4  = tid & 7;

    // prologue: chunk 0
    {
        char* sa = smem;
        char* sbm = smem + 16384;
#pragma unroll
        for (int i = 0; i < 4; ++i) {
            int row = lrow + i * 32;
            stash(sa,  row, lk4, *(const float4*)(Abase + (size_t)row * K + lk4 * 4));
            stash(sbm, row, lk4, *(const float4*)(Bbase + (size_t)row * K + lk4 * 4));
        }
    }
    __syncthreads();

    int buf = 0;
    for (int c = 0; c < nchunks; ++c) {
        const uint32_t sa_u = smem_u32(smem + buf * STAGE);
        const uint32_t sb_u = sa_u + 16384;
        const bool has = (c + 1 < nchunks);
        const float* Anext = Abase + (size_t)(c + 1) * MBK;
        const float* Bnext = Bbase + (size_t)(c + 1) * MBK;
        char* dst = smem + (buf ^ 1) * STAGE;

        float4 pref[4];
        if (has) {
#pragma unroll
            for (int i = 0; i < 4; ++i) {
                int row = lrow + i * 32;
                pref[i] = *(const float4*)(Anext + (size_t)row * K + lk4 * 4);
            }
        }

#pragma unroll
        for (int ks = 0; ks < 2; ++ks) {
            // ---- load fragments ----
            uint32_t ah[4][4], bh[2][4], bl[2][4];
#pragma unroll
            for (int am = 0; am < 4; ++am) {
                int row = rowA_base + am * 16;
                int ch = 0 * 4 + ks * 2 + khA_sel;      // hi
                ldmx4(ah[am], sa_u + row * 128 + (((ch ^ (row & 7)) << 4)));
            }
#pragma unroll
            for (int pr = 0; pr < 2; ++pr) {
                int row = rowB_base + pr * 16;
                int chh = 0 * 4 + ks * 2 + khB_sel;
                int chl = 1 * 4 + ks * 2 + khB_sel;
                ldmx4(bh[pr], sb_u + row * 128 + (((chh ^ (row & 7)) << 4)));
                ldmx4(bl[pr], sb_u + row * 128 + (((chl ^ (row & 7)) << 4)));
            }
            // ---- Ah*Bh + Ah*Bl ----
#pragma unroll
            for (int am = 0; am < 4; ++am)
#pragma unroll
                for (int an = 0; an < 4; ++an) {
                    mma16816(acc[am][an], ah[am], &bh[an >> 1][(an & 1) * 2]);
                    mma16816(acc[am][an], ah[am], &bl[an >> 1][(an & 1) * 2]);
                }
            // ---- Al*Bh ----
            uint32_t al[4][4];
#pragma unroll
            for (int am = 0; am < 4; ++am) {
                int row = rowA_base + am * 16;
                int ch = 1 * 4 + ks * 2 + khA_sel;      // lo
                ldmx4(al[am], sa_u + row * 128 + (((ch ^ (row & 7)) << 4)));
            }
#pragma unroll
            for (int am = 0; am < 4; ++am)
#pragma unroll
                for (int an = 0; an < 4; ++an)
                    mma16816(acc[am][an], al[am], &bh[an >> 1][(an & 1) * 2]);

            // interleave next-chunk loads between the two k-steps
            if (ks == 0 && has) {
#pragma unroll
                for (int i = 0; i < 4; ++i)
                    stash(dst, lrow + i * 32, lk4, pref[i]);
#pragma unroll
                for (int i = 0; i < 4; ++i) {
                    int row = lrow + i * 32;
                    pref[i] = *(const float4*)(Bnext + (size_t)row * K + lk4 * 4);
                }
            }
        }
        if (has) {
#pragma unroll
            for (int i = 0; i < 4; ++i)
                stash(dst + 16384, lrow + i * 32, lk4, pref[i]);
        }
        __syncthreads();
        buf ^= 1;
    }

    // ---- epilogue ----
#pragma unroll
    for (int am = 0; am < 4; ++am) {
        const int row0 = bm + warp_m * 64 + am * 16 + g;
#pragma unroll
        for (int an = 0; an < 4; ++an) {
            const int col = bn + warp_n * 32 + an * 8 + tig * 2;
            const float* d = acc[am][an];
            float2 o0 = make_float2(d[0], d[1]);
            float2 o1 = make_float2(d[2], d[3]);
            const size_t p0 = (size_t)row0 * N + col;
            const size_t p1 = (size_t)(row0 + 8) * N + col;
            if (EPI == 1) {
                float2 b2 = *(const float2*)(bias + col);
                float2 r0 = *(const float2*)(res + p0);
                float2 r1 = *(const float2*)(res + p1);
                o0.x += b2.x + r0.x; o0.y += b2.y + r0.y;
                o1.x += b2.x + r1.x; o1.y += b2.y + r1.y;
            } else if (EPI == 2) {
                float2 b2 = *(const float2*)(bias + col);
                o0.x += b2.x; o0.y += b2.y;
                o1.x += b2.x; o1.y += b2.y;
            } else if (EPI == 3) {
                float2 b2 = *(const float2*)(bias + col);
                float2 g0 = *(const float2*)(res + p0);
                float2 g1 = *(const float2*)(res + p1);
                o0.x = siluf(g0.x) * (o0.x + b2.x);
                o0.y = siluf(g0.y) * (o0.y + b2.y);
                o1.x = siluf(g1.x) * (o1.x + b2.x);
                o1.y = siluf(g1.y) * (o1.y + b2.y);
            }
            *(float2*)(C + p0) = o0;
            *(float2*)(C + p1) = o1;
        }
    }
}

// ---------------------------------------------------------------------------
// RMSNorm (optionally with sigmoid-gated blend of x and x_token)
// ---------------------------------------------------------------------------
__global__ __launch_bounds__(256)
void rms_kernel(const float* __restrict__ X, const float* __restrict__ XT,
                const float* __restrict__ lcw, const float* __restrict__ W,
                float* __restrict__ out, int gated)
{
    const int row = blockIdx.x;
    const int tid = threadIdx.x;
    float4 xv = ((const float4*)(X + (size_t)row * 1024))[tid];
    if (gated) {
        float lc = 1.0f / (1.0f + expf(-lcw[0]));
        float om = 1.0f - lc;
        float4 tv = ((const float4*)(XT + (size_t)row * 1024))[tid];
        xv.x = lc * xv.x + om * tv.x;
        xv.y = lc * xv.y + om * tv.y;
        xv.z = lc * xv.z + om * tv.z;
        xv.w = lc * xv.w + om * tv.w;
    }
    float ss = xv.x * xv.x + xv.y * xv.y + xv.z * xv.z + xv.w * xv.w;
#pragma unroll
    for (int o = 16; o > 0; o >>= 1) ss += __shfl_xor_sync(0xffffffffu, ss, o);
    __shared__ float red[8];
    if ((tid & 31) == 0) red[tid >> 5] = ss;
    __syncthreads();
    float tot = red[0] + red[1] + red[2] + red[3] + red[4] + red[5] + red[6] + red[7];
    float rinv = rsqrtf(tot * (1.0f / 1024.0f) + 1e-5f);
    float4 wv = ((const float4*)W)[tid];
    float4 ov;
    ov.x = xv.x * rinv * wv.x;
    ov.y = xv.y * rinv * wv.y;
    ov.z = xv.z * rinv * wv.z;
    ov.w = xv.w * rinv * wv.w;
    ((float4*)(out + (size_t)row * 1024))[tid] = ov;
}

// ---------------------------------------------------------------------------
// Causal attention, flash-style online softmax (fp32, f32x2 FMA).
// ---------------------------------------------------------------------------
__global__ __launch_bounds__(128)
void attn_kernel(const float* __restrict__ Q, const float* __restrict__ Kg,
                 const float* __restrict__ V, float* __restrict__ O)
{
    __shared__ float Ks[64][64];
    __shared__ float Vs[64][64];

    const int qt = blockIdx.x, h = blockIdx.y, b = blockIdx.z;
    const int q0 = qt * 128;
    const int tid = threadIdx.x;
    const int qidx = q0 + tid;

    unsigned long long q2[32], o2[32];
    {
        const float4* qp = (const float4*)(Q + (((size_t)(b * 2048 + qidx)) * 16 + h) * 64);
#pragma unroll
        for (int i = 0; i < 16; ++i) {
            float4 v = qp[i];
            q2[2 * i]     = pk2(v.x, v.y);
            q2[2 * i + 1] = pk2(v.z, v.w);
        }
    }
#pragma unroll
    for (int i = 0; i < 32; ++i) o2[i] = 0ULL;

    float mval = __int_as_float(0xff800000);  // -inf
    float l = 0.0f;
    const float scale = 0.03125f;

    for (int kt = 0; kt < q0 + 128; kt += 64) {
        __syncthreads();
#pragma unroll
        for (int i = 0; i < 8; ++i) {
            int u = tid + i * 128;
            int row = u >> 4, c4 = u & 15;
            ((float4*)&Ks[row][0])[c4] =
                *(const float4*)(Kg + (size_t)(kt + row) * 1024 + h * 64 + c4 * 4);
            ((float4*)&Vs[row][0])[c4] =
                *(const float4*)(V + (((size_t)(b * 2048 + kt + row)) * 16 + h) * 64 + c4 * 4);
        }
        __syncthreads();

        int jmax = qidx - kt + 1;
        if (jmax > 64) jmax = 64;
        for (int j = 0; j < jmax; ++j) {
            const unsigned long long* kp = (const unsigned long long*)&Ks[j][0];
            unsigned long long sa = 0ULL, sbb = 0ULL, sc = 0ULL, sd = 0ULL;
#pragma unroll
            for (int d = 0; d < 32; d += 4) {
                ffma2(sa,  q2[d],     kp[d]);
                ffma2(sbb, q2[d + 1], kp[d + 1]);
                ffma2(sc,  q2[d + 2], kp[d + 2]);
                ffma2(sd,  q2[d + 3], kp[d + 3]);
            }
            float2 pa = upk2(sa), pb = upk2(sbb), pc = upk2(sc), pd = upk2(sd);
            float s = ((pa.x + pa.y) + (pb.x + pb.y) + (pc.x + pc.y) + (pd.x + pd.y)) * scale;

            const unsigned long long* vp = (const unsigned long long*)&Vs[j][0];
            if (s <= mval) {
                float p = __expf(s - mval);
                l += p;
                unsigned long long pd2 = pk2(p, p);
#pragma unroll
                for (int d = 0; d < 32; ++d) ffma2(o2[d], pd2, vp[d]);
            } else {
                float f = __expf(mval - s);   // exp(-inf)=0 on first key
                mval = s;
                l = l * f + 1.0f;
                unsigned long long fd = pk2(f, f);
#pragma unroll
                for (int d = 0; d < 32; ++d) {
                    unsigned long long t = vp[d];    // t = o*f + v
                    ffma2(t, o2[d], fd);
                    o2[d] = t;
                }
            }
        }
    }

    float inv = 1.0f / l;
    unsigned long long iv = pk2(inv, inv);
    float* op = O + (((size_t)(b * 2048 + qidx)) * 16 + h) * 64;
#pragma unroll
    for (int i = 0; i < 16; ++i) {
        float2 p0 = upk2(mul2(o2[2 * i], iv));
        float2 p1 = upk2(mul2(o2[2 * i + 1], iv));
        *(float4*)(op + i * 4) = make_float4(p0.x, p0.y, p1.x, p1.y);
    }
}

// ---------------------------------------------------------------------------
// Launch
// ---------------------------------------------------------------------------
extern "C" void kernel_launch(void* const* d_in, const int* in_sizes, int n_in,
                              void* d_out, int out_size)
{
    const float* x       = (const float*)d_in[0];
    const float* x_token = (const float*)d_in[1];
    const float* pos_emb = (const float*)d_in[2];
    const float* lcw     = (const float*)d_in[3];
    const float* Wq      = (const float*)d_in[4];
    const float* Wk      = (const float*)d_in[5];
    const float* Wv      = (const float*)d_in[6];
    const float* proj_w  = (const float*)d_in[7];
    const float* proj_b  = (const float*)d_in[8];
    const float* w1_w    = (const float*)d_in[9];
    const float* w1_b    = (const float*)d_in[10];
    const float* w2_w    = (const float*)d_in[11];
    const float* w2_b    = (const float*)d_in[12];
    const float* w3_w    = (const float*)d_in[13];
    const float* w3_b    = (const float*)d_in[14];
    const float* n1w     = (const float*)d_in[15];
    const float* n2w     = (const float*)d_in[16];
    float* out = (float*)d_out;

    float *xn, *q, *k, *v, *at, *xm, *hbuf;
    cudaGetSymbolAddress((void**)&xn,   g_xn);
    cudaGetSymbolAddress((void**)&q,    g_q);
    cudaGetSymbolAddress((void**)&k,    g_k);
    cudaGetSymbolAddress((void**)&v,    g_v);
    cudaGetSymbolAddress((void**)&at,   g_at);
    cudaGetSymbolAddress((void**)&xm,   g_xm);
    cudaGetSymbolAddress((void**)&hbuf, g_h);

    cudaFuncSetAttribute(mma_gemm<0>, cudaFuncAttributeMaxDynamicSharedMemorySize, MM_SMEM);
    cudaFuncSetAttribute(mma_gemm<1>, cudaFuncAttributeMaxDynamicSharedMemorySize, MM_SMEM);
    cudaFuncSetAttribute(mma_gemm<2>, cudaFuncAttributeMaxDynamicSharedMemorySize, MM_SMEM);
    cudaFuncSetAttribute(mma_gemm<3>, cudaFuncAttributeMaxDynamicSharedMemorySize, MM_SMEM);

    // 1) gated rmsnorm -> xn
    rms_kernel<<<4096, 256>>>(x, x_token, lcw, n1w, xn, 1);
    // 2) q = xn @ Wq^T ; k = pos_emb @ Wk^T ; v = xn @ Wv^T
    mma_gemm<0><<<dim3(8, 32), 256, MM_SMEM>>>(xn,      Wq, nullptr, nullptr, q, 4096, 1024, 1024);
    mma_gemm<0><<<dim3(8, 16), 256, MM_SMEM>>>(pos_emb, Wk, nullptr, nullptr, k, 2048, 1024, 1024);
    mma_gemm<0><<<dim3(8, 32), 256, MM_SMEM>>>(xn,      Wv, nullptr, nullptr, v, 4096, 1024, 1024);
    // 3) causal attention
    attn_kernel<<<dim3(16, 16, 2), 128>>>(q, k, v, at);
    // 4) x_mid = x + attn @ proj_w^T + proj_b
    mma_gemm<1><<<dim3(8, 32), 256, MM_SMEM>>>(at, proj_w, proj_b, x, xm, 4096, 1024, 1024);
    // 5) xn2 = rmsnorm(x_mid)
    rms_kernel<<<4096, 256>>>(xm, nullptr, nullptr, n2w, xn, 0);
    // 6) h1 = xn2 @ w1^T + b1 ; h = silu(h1) * (xn2 @ w3^T + b3)  (in place)
    mma_gemm<2><<<dim3(32, 32), 256, MM_SMEM>>>(xn, w1_w, w1_b, nullptr, hbuf, 4096, 4096, 1024);
    mma_gemm<3><<<dim3(32, 32), 256, MM_SMEM>>>(xn, w3_w, w3_b, hbuf,    hbuf, 4096, 4096, 1024);
    // 7) out = x_mid + h @ w2^T + b2
    mma_gemm<1><<<dim3(8, 32), 256, MM_SMEM>>>(hbuf, w2_w, w2_b, xm, out, 4096, 1024, 4096);
}